// round 1
// baseline (speedup 1.0000x reference)
#include <cuda_runtime.h>
#include <cuda_bf16.h>

// ---------------- problem constants ----------------
#define S_LEN   661500
#define N_FFT   2048
#define HOP     512
#define N_HALF  1024            // complex FFT size (real-packed)
#define T_FRAMES 1292           // 1 + (S + 2*1024 - 2048)/512
#define N_CH    16              // B*C = 8*2
#define NFRAMES (N_CH * T_FRAMES)   // 20672
#define N_BINS  1025
#define KP      1040            // padded K (multiple of 16, float4-aligned)
#define N_MELS  128

// ---------------- device scratch (statics: no allocation allowed) ----------------
__device__ float  g_power[(size_t)NFRAMES * KP];   // [frame][bin], zero-padded tail
__device__ float  g_fb[(size_t)N_MELS * KP];       // padded mel filterbank
__device__ float2 g_tw1024[512];                   // exp(-2*pi*i*k/1024), k<512
__device__ float2 g_tw2048[1025];                  // exp(-2*pi*i*k/2048), k<=1024
__device__ float  g_win[N_FFT];                    // periodic hann

// ---------------- init: window, twiddles, padded filterbank ----------------
__global__ void init_kernel(const float* __restrict__ fb) {
    int idx = blockIdx.x * blockDim.x + threadIdx.x;
    if (idx < N_MELS * KP) {
        int row = idx / KP;
        int k   = idx - row * KP;
        g_fb[idx] = (k < N_BINS) ? fb[row * N_BINS + k] : 0.0f;
    }
    if (idx < N_FFT) {
        // 0.5 - 0.5*cos(2*pi*n/N) = 0.5 - 0.5*cospi(n/1024)
        g_win[idx] = 0.5f - 0.5f * cospif((float)idx / 1024.0f);
    }
    if (idx < 512) {
        float s, c;
        sincospif(-(float)idx / 512.0f, &s, &c);   // angle = -2*pi*idx/1024
        g_tw1024[idx] = make_float2(c, s);
    }
    if (idx < 1025) {
        float s, c;
        sincospif(-(float)idx / 1024.0f, &s, &c);  // angle = -2*pi*idx/2048
        g_tw2048[idx] = make_float2(c, s);
    }
}

// ---------------- per-frame windowed rFFT -> power spectrum ----------------
__global__ __launch_bounds__(256) void fft_power_kernel(const float* __restrict__ x) {
    __shared__ float  zr[N_HALF];
    __shared__ float  zi[N_HALF];
    __shared__ float2 tw[512];

    const int tid = threadIdx.x;
    const int f   = blockIdx.x;
    const int g   = f / T_FRAMES;
    const int t   = f - g * T_FRAMES;
    const int b   = g >> 1;
    const int c   = g & 1;
    const float* xb = x + (size_t)b * S_LEN * 2 + c;   // channel-interleaved

    for (int i = tid; i < 512; i += 256) tw[i] = g_tw1024[i];

    // load windowed, reflect-padded frame; pack reals pairwise into complex,
    // write in bit-reversed order (10-bit) so DIT stages yield natural order.
    const int base = t * HOP - 1024;
    for (int k = tid; k < N_HALF; k += 256) {
        int n0 = 2 * k;
        int p0 = base + n0;
        p0 = (p0 < 0) ? -p0 : ((p0 >= S_LEN) ? (2 * (S_LEN - 1) - p0) : p0);
        int p1 = base + n0 + 1;
        p1 = (p1 < 0) ? -p1 : ((p1 >= S_LEN) ? (2 * (S_LEN - 1) - p1) : p1);
        float v0 = g_win[n0]     * xb[(size_t)p0 * 2];
        float v1 = g_win[n0 + 1] * xb[(size_t)p1 * 2];
        int r = (int)(__brev((unsigned)k) >> 22);
        zr[r] = v0;
        zi[r] = v1;
    }
    __syncthreads();

    // iterative radix-2 DIT, 10 stages
    for (int len = 2; len <= N_HALF; len <<= 1) {
        const int half  = len >> 1;
        const int tstep = N_HALF / len;
        for (int bf = tid; bf < (N_HALF / 2); bf += 256) {
            int j  = bf & (half - 1);
            int i0 = ((bf ^ j) << 1) | j;
            int i1 = i0 + half;
            float2 w = tw[j * tstep];
            float xr = zr[i1], xi = zi[i1];
            float tr = w.x * xr - w.y * xi;
            float ti = w.x * xi + w.y * xr;
            float ur = zr[i0], ui = zi[i0];
            zr[i1] = ur - tr; zi[i1] = ui - ti;
            zr[i0] = ur + tr; zi[i0] = ui + ti;
        }
        __syncthreads();
    }

    // real-FFT unpack + power, bins 0..1024
    float* pr = g_power + (size_t)f * KP;
    for (int k = tid; k <= N_HALF; k += 256) {
        int ka = k & (N_HALF - 1);
        int kb = (N_HALF - k) & (N_HALF - 1);
        float ar = zr[ka], ai = zi[ka];
        float br = zr[kb], bi = -zi[kb];
        float er  = 0.5f * (ar + br);
        float ei  = 0.5f * (ai + bi);
        float dr  = ar - br;
        float di  = ai - bi;
        float orr = 0.5f * di;
        float oi  = -0.5f * dr;
        float2 w = g_tw2048[k];
        float xr2 = er + w.x * orr - w.y * oi;
        float xi2 = ei + w.x * oi + w.y * orr;
        pr[k] = xr2 * xr2 + xi2 * xi2;
    }
    if (tid < (KP - N_BINS)) pr[N_BINS + tid] = 0.0f;   // zero K padding
}

// ---------------- mel GEMM: out[m,n] = sum_k fb[m,k] * P[n,k] ----------------
// M=128 (exact), N=20672 = 323*64 (exact), K=1040 (exact *16) -> no guards.
__global__ __launch_bounds__(128) void mel_gemm_kernel(float* __restrict__ out) {
    __shared__ float As[16][N_MELS];   // [k][m]
    __shared__ float Bs[16][64];       // [k][n]

    const int tid = threadIdx.x;
    const int tm  = tid & 15;          // 16 m-groups
    const int tn  = tid >> 4;          // 8 n-groups
    const int n0  = blockIdx.x * 64;

    float acc[8][8];
#pragma unroll
    for (int i = 0; i < 8; i++)
#pragma unroll
        for (int j = 0; j < 8; j++) acc[i][j] = 0.0f;

    const int lr = tid >> 2;           // 0..31
    const int lk = (tid & 3) * 4;      // 0,4,8,12

    for (int k0 = 0; k0 < KP; k0 += 16) {
#pragma unroll
        for (int i = 0; i < 4; i++) {
            int row = lr + i * 32;
            float4 v = *(const float4*)(g_fb + (size_t)row * KP + k0 + lk);
            As[lk + 0][row] = v.x;
            As[lk + 1][row] = v.y;
            As[lk + 2][row] = v.z;
            As[lk + 3][row] = v.w;
        }
#pragma unroll
        for (int i = 0; i < 2; i++) {
            int row = lr + i * 32;
            float4 v = *(const float4*)(g_power + (size_t)(n0 + row) * KP + k0 + lk);
            Bs[lk + 0][row] = v.x;
            Bs[lk + 1][row] = v.y;
            Bs[lk + 2][row] = v.z;
            Bs[lk + 3][row] = v.w;
        }
        __syncthreads();

#pragma unroll
        for (int kk = 0; kk < 16; kk++) {
            float4 a0 = *(const float4*)&As[kk][tm * 8];
            float4 a1 = *(const float4*)&As[kk][tm * 8 + 4];
            float4 b0 = *(const float4*)&Bs[kk][tn * 8];
            float4 b1 = *(const float4*)&Bs[kk][tn * 8 + 4];
            float a[8] = {a0.x, a0.y, a0.z, a0.w, a1.x, a1.y, a1.z, a1.w};
            float bv[8] = {b0.x, b0.y, b0.z, b0.w, b1.x, b1.y, b1.z, b1.w};
#pragma unroll
            for (int i = 0; i < 8; i++)
#pragma unroll
                for (int j = 0; j < 8; j++) acc[i][j] = fmaf(a[i], bv[j], acc[i][j]);
        }
        __syncthreads();
    }

    // epilogue: n = (b*2+c)*T + t ; out[((b*128+m)*T + t)*2 + c]
#pragma unroll
    for (int j = 0; j < 8; j++) {
        int n  = n0 + tn * 8 + j;
        int gc = n / T_FRAMES;
        int t  = n - gc * T_FRAMES;
        int bb = gc >> 1;
        int cc = gc & 1;
#pragma unroll
        for (int i = 0; i < 8; i++) {
            int m = tm * 8 + i;
            out[(((size_t)bb * N_MELS + m) * T_FRAMES + t) * 2 + cc] = acc[i][j];
        }
    }
}

// ---------------- entry point ----------------
extern "C" void kernel_launch(void* const* d_in, const int* in_sizes, int n_in,
                              void* d_out, int out_size) {
    const float* x  = (const float*)d_in[0];   // (8, 661500, 2) f32
    const float* fb = (const float*)d_in[1];   // (128, 1025)   f32
    float* out = (float*)d_out;                // (8, 128, 1292, 2) f32

    init_kernel<<<(N_MELS * KP + 255) / 256, 256>>>(fb);
    fft_power_kernel<<<NFRAMES, 256>>>(x);
    mel_gemm_kernel<<<NFRAMES / 64, 128>>>(out);
}